// round 1
// baseline (speedup 1.0000x reference)
#include <cuda_runtime.h>

#define N_FFT   8192
#define T_LEN   4096
#define PAD     2048
#define B_MAX   64
#define S_MAX   128
#define THREADS 512

// Scratch (device globals: allocation-free)
__device__ float2 g_tw[2048];              // exp(-2*pi*i*k/8192), k in [0,2048)
__device__ float2 g_F[B_MAX * N_FFT];      // forward spectra, natural order

// ---------------------------------------------------------------------------
// Twiddle table init (fp64 accurate)
// ---------------------------------------------------------------------------
__global__ void twiddle_init_kernel() {
    int k = blockIdx.x * blockDim.x + threadIdx.x;
    if (k < 2048) {
        double a = (6.283185307179586476925287 / 8192.0) * (double)k;
        g_tw[k] = make_float2((float)cos(a), (float)(-sin(a)));
    }
}

// ---------------------------------------------------------------------------
// One Stockham radix-4 stage. Natural-order autosort, ping-pong buffers.
// m = 1<<mshift (elements already combined), l = 2048/m groups.
// Reads are perfectly coalesced: x[idx + 2048*t].
// ---------------------------------------------------------------------------
template<bool FWD>
__device__ __forceinline__ void radix4_stage(
    const float* __restrict__ xr, const float* __restrict__ xi,
    float* __restrict__ yr, float* __restrict__ yi,
    int mshift, int tid)
{
    const int m = 1 << mshift;
    #pragma unroll
    for (int q = 0; q < (N_FFT / 4) / THREADS; ++q) {
        int idx = tid + q * THREADS;          // 0..2047
        int k   = idx & (m - 1);
        int jm  = idx - k;                    // j*m, also the twiddle index

        float ar = xr[idx],        ai = xi[idx];
        float br = xr[idx + 2048], bi = xi[idx + 2048];
        float cr = xr[idx + 4096], ci = xi[idx + 4096];
        float dr = xr[idx + 6144], di = xi[idx + 6144];

        float t0r = ar + cr, t0i = ai + ci;
        float t1r = ar - cr, t1i = ai - ci;
        float t2r = br + dr, t2i = bi + di;
        float ur  = br - dr, ui  = bi - di;
        // t3 = (b-d) * (-i) forward, (+i) inverse
        float t3r, t3i;
        if (FWD) { t3r =  ui; t3i = -ur; }
        else     { t3r = -ui; t3i =  ur; }

        float2 w  = g_tw[jm];
        float w1r = w.x;
        float w1i = FWD ? w.y : -w.y;
        float w2r = w1r * w1r - w1i * w1i;
        float w2i = 2.0f * w1r * w1i;
        float w3r = w2r * w1r - w2i * w1i;
        float w3i = w2r * w1i + w2i * w1r;

        int o = idx + 3 * jm;                 // k + 4*m*j
        yr[o]         = t0r + t2r;
        yi[o]         = t0i + t2i;
        float e1r = t1r + t3r, e1i = t1i + t3i;
        yr[o + m]     = e1r * w1r - e1i * w1i;
        yi[o + m]     = e1r * w1i + e1i * w1r;
        float e2r = t0r - t2r, e2i = t0i - t2i;
        yr[o + 2 * m] = e2r * w2r - e2i * w2i;
        yi[o + 2 * m] = e2r * w2i + e2i * w2r;
        float e3r = t1r - t3r, e3i = t1i - t3i;
        yr[o + 3 * m] = e3r * w3r - e3i * w3i;
        yi[o + 3 * m] = e3r * w3i + e3i * w3r;
    }
}

// ---------------------------------------------------------------------------
// Forward FFT of the reflect-padded input. One CTA per batch row.
// 6 radix-4 stages + final radix-2 (w=1) writing spectra to g_F.
// ---------------------------------------------------------------------------
extern __shared__ float smem_f[];

__global__ void __launch_bounds__(THREADS, 1)
fwd_fft_kernel(const float* __restrict__ in)
{
    float* Ar = smem_f;
    float* Ai = smem_f + N_FFT;
    float* Br = smem_f + 2 * N_FFT;
    float* Bi = smem_f + 3 * N_FFT;

    const int b   = blockIdx.x;
    const int tid = threadIdx.x;
    const float* x = in + b * T_LEN;

    // reflect pad: [x[2047..0], x[0..4095], x[4095..2048]]
    for (int i = tid; i < N_FFT; i += THREADS) {
        int src;
        if (i < PAD)              src = PAD - 1 - i;
        else if (i < PAD + T_LEN) src = i - PAD;
        else                      src = (2 * T_LEN + PAD - 1) - i;   // 10239 - i
        Ar[i] = x[src];
        Ai[i] = 0.0f;
    }
    __syncthreads();

    radix4_stage<true>(Ar, Ai, Br, Bi,  0, tid); __syncthreads();
    radix4_stage<true>(Br, Bi, Ar, Ai,  2, tid); __syncthreads();
    radix4_stage<true>(Ar, Ai, Br, Bi,  4, tid); __syncthreads();
    radix4_stage<true>(Br, Bi, Ar, Ai,  6, tid); __syncthreads();
    radix4_stage<true>(Ar, Ai, Br, Bi,  8, tid); __syncthreads();
    radix4_stage<true>(Br, Bi, Ar, Ai, 10, tid); __syncthreads();

    // final radix-2 (l=1, m=4096, twiddle = 1), write to global scratch
    float2* F = g_F + b * N_FFT;
    for (int k = tid; k < N_FFT / 2; k += THREADS) {
        float u_r = Ar[k],        u_i = Ai[k];
        float v_r = Ar[k + 4096], v_i = Ai[k + 4096];
        F[k]        = make_float2(u_r + v_r, u_i + v_i);
        F[k + 4096] = make_float2(u_r - v_r, u_i - v_i);
    }
}

// ---------------------------------------------------------------------------
// Inverse FFT per (batch, scale): G = F_b * wft_s / n, inverse Stockham,
// final radix-2 fused with log(abs) + store of the middle T samples.
// ---------------------------------------------------------------------------
__global__ void __launch_bounds__(THREADS, 1)
cwt_ifft_kernel(const float* __restrict__ wft, float* __restrict__ out, int S)
{
    float* Ar = smem_f;
    float* Ai = smem_f + N_FFT;
    float* Br = smem_f + 2 * N_FFT;
    float* Bi = smem_f + 3 * N_FFT;

    const int tid = threadIdx.x;
    const int s   = blockIdx.x % S;
    const int b   = blockIdx.x / S;

    const float2* F = g_F + b * N_FFT;
    const float*  w = wft + s * N_FFT;
    const float inv_n = 1.0f / (float)N_FFT;

    for (int i = tid; i < N_FFT; i += THREADS) {
        float2 f = F[i];
        float  g = w[i] * inv_n;
        Ar[i] = f.x * g;
        Ai[i] = f.y * g;
    }
    __syncthreads();

    radix4_stage<false>(Ar, Ai, Br, Bi,  0, tid); __syncthreads();
    radix4_stage<false>(Br, Bi, Ar, Ai,  2, tid); __syncthreads();
    radix4_stage<false>(Ar, Ai, Br, Bi,  4, tid); __syncthreads();
    radix4_stage<false>(Br, Bi, Ar, Ai,  6, tid); __syncthreads();
    radix4_stage<false>(Ar, Ai, Br, Bi,  8, tid); __syncthreads();
    radix4_stage<false>(Br, Bi, Ar, Ai, 10, tid); __syncthreads();

    // Final radix-2 (l=1, m=4096, w=1). Time sample at position p:
    //   p = k        -> u + v   (need p in [2048,6144) => k in [2048,4096))
    //   p = k + 4096 -> u - v   (need k in [0,2048))
    // Each k emits exactly one needed output; fuse log|.| + global store.
    float* o = out + (size_t)blockIdx.x * T_LEN;   // blockIdx.x == b*S + s
    for (int k = tid; k < N_FFT / 2; k += THREADS) {
        float u_r = Ar[k],        u_i = Ai[k];
        float v_r = Ar[k + 4096], v_i = Ai[k + 4096];
        float rr, ri; int t;
        if (k >= PAD) { rr = u_r + v_r; ri = u_i + v_i; t = k - PAD; }
        else          { rr = u_r - v_r; ri = u_i - v_i; t = k + PAD; }
        o[t] = 0.5f * logf(rr * rr + ri * ri);
    }
}

// ---------------------------------------------------------------------------
extern "C" void kernel_launch(void* const* d_in, const int* in_sizes, int n_in,
                              void* d_out, int out_size)
{
    const float* in  = (const float*)d_in[0];
    const float* wft = (const float*)d_in[1];
    float* out = (float*)d_out;

    const int B = in_sizes[0] / T_LEN;     // 64
    const int S = in_sizes[1] / N_FFT;     // 75

    const int smem_bytes = 4 * N_FFT * sizeof(float);   // 128 KB
    cudaFuncSetAttribute(fwd_fft_kernel,
                         cudaFuncAttributeMaxDynamicSharedMemorySize, smem_bytes);
    cudaFuncSetAttribute(cwt_ifft_kernel,
                         cudaFuncAttributeMaxDynamicSharedMemorySize, smem_bytes);

    twiddle_init_kernel<<<4, THREADS>>>();
    fwd_fft_kernel<<<B, THREADS, smem_bytes>>>(in);
    cwt_ifft_kernel<<<B * S, THREADS, smem_bytes>>>(wft, out, S);
}

// round 2
// speedup vs baseline: 1.7092x; 1.7092x over previous
#include <cuda_runtime.h>

#define N_FFT   8192
#define HALF    4096
#define T_LEN   4096
#define PAD     2048
#define B_MAX   64
#define FTH     512      // threads, forward kernel
#define ITH     512      // threads, inverse kernel

// Scratch (device globals: allocation-free)
__device__ float2 g_tw[4096];              // exp(-2*pi*i*k/8192), k in [0,4096)
__device__ float2 g_F[B_MAX * N_FFT];      // forward spectra, natural order

// ---------------------------------------------------------------------------
// Twiddle table init (fp32 sincospif: fast, ~1ulp of pi-scaled arg)
// ---------------------------------------------------------------------------
__global__ void twiddle_init_kernel() {
    int k = blockIdx.x * blockDim.x + threadIdx.x;
    if (k < 4096) {
        float s, c;
        sincospif((float)k * (1.0f / 4096.0f), &s, &c);
        g_tw[k] = make_float2(c, -s);
    }
}

// ---------------------------------------------------------------------------
// Radix-4 Stockham stage for the 8192-pt FORWARD FFT (twiddle = g_tw[jm]).
// ---------------------------------------------------------------------------
__device__ __forceinline__ void r4f_8k(
    const float* __restrict__ xr, const float* __restrict__ xi,
    float* __restrict__ yr, float* __restrict__ yi,
    int mshift, int tid)
{
    const int m = 1 << mshift;
    #pragma unroll
    for (int q = 0; q < (N_FFT / 4) / FTH; ++q) {
        int idx = tid + q * FTH;
        int k   = idx & (m - 1);
        int jm  = idx - k;

        float ar = xr[idx],        ai = xi[idx];
        float br = xr[idx + 2048], bi = xi[idx + 2048];
        float cr = xr[idx + 4096], ci = xi[idx + 4096];
        float dr = xr[idx + 6144], di = xi[idx + 6144];

        float t0r = ar + cr, t0i = ai + ci;
        float t1r = ar - cr, t1i = ai - ci;
        float t2r = br + dr, t2i = bi + di;
        float ur  = br - dr, ui  = bi - di;
        float t3r =  ui, t3i = -ur;                 // forward: *(-i)

        float2 w  = g_tw[jm];
        float w1r = w.x, w1i = w.y;
        float w2r = w1r * w1r - w1i * w1i;
        float w2i = 2.0f * w1r * w1i;
        float w3r = w2r * w1r - w2i * w1i;
        float w3i = w2r * w1i + w2i * w1r;

        int o = idx + 3 * jm;
        yr[o]         = t0r + t2r;
        yi[o]         = t0i + t2i;
        float e1r = t1r + t3r, e1i = t1i + t3i;
        yr[o + m]     = e1r * w1r - e1i * w1i;
        yi[o + m]     = e1r * w1i + e1i * w1r;
        float e2r = t0r - t2r, e2i = t0i - t2i;
        yr[o + 2 * m] = e2r * w2r - e2i * w2i;
        yi[o + 2 * m] = e2r * w2i + e2i * w2r;
        float e3r = t1r - t3r, e3i = t1i - t3i;
        yr[o + 3 * m] = e3r * w3r - e3i * w3i;
        yi[o + 3 * m] = e3r * w3i + e3i * w3r;
    }
}

// ---------------------------------------------------------------------------
// Forward 8192-pt FFT of the reflect-padded input. One CTA per batch row.
// ---------------------------------------------------------------------------
extern __shared__ float smem_f[];

__global__ void __launch_bounds__(FTH, 1)
fwd_fft_kernel(const float* __restrict__ in)
{
    float* Ar = smem_f;
    float* Ai = smem_f + N_FFT;
    float* Br = smem_f + 2 * N_FFT;
    float* Bi = smem_f + 3 * N_FFT;

    const int b   = blockIdx.x;
    const int tid = threadIdx.x;
    const float* x = in + b * T_LEN;

    for (int i = tid; i < N_FFT; i += FTH) {
        int src;
        if (i < PAD)              src = PAD - 1 - i;
        else if (i < PAD + T_LEN) src = i - PAD;
        else                      src = (2 * T_LEN + PAD - 1) - i;
        Ar[i] = x[src];
        Ai[i] = 0.0f;
    }
    __syncthreads();

    r4f_8k(Ar, Ai, Br, Bi,  0, tid); __syncthreads();
    r4f_8k(Br, Bi, Ar, Ai,  2, tid); __syncthreads();
    r4f_8k(Ar, Ai, Br, Bi,  4, tid); __syncthreads();
    r4f_8k(Br, Bi, Ar, Ai,  6, tid); __syncthreads();
    r4f_8k(Ar, Ai, Br, Bi,  8, tid); __syncthreads();
    r4f_8k(Br, Bi, Ar, Ai, 10, tid); __syncthreads();

    float2* F = g_F + b * N_FFT;
    for (int k = tid; k < N_FFT / 2; k += FTH) {
        float u_r = Ar[k],        u_i = Ai[k];
        float v_r = Ar[k + 4096], v_i = Ai[k + 4096];
        F[k]        = make_float2(u_r + v_r, u_i + v_i);
        F[k + 4096] = make_float2(u_r - v_r, u_i - v_i);
    }
}

// ---------------------------------------------------------------------------
// Radix-4 Stockham stage for the 4096-pt INVERSE FFT (twiddle = conj(g_tw[2*jm])).
// ---------------------------------------------------------------------------
__device__ __forceinline__ void r4i_4k(
    const float* __restrict__ xr, const float* __restrict__ xi,
    float* __restrict__ yr, float* __restrict__ yi,
    int mshift, int tid)
{
    const int m = 1 << mshift;
    #pragma unroll
    for (int q = 0; q < (HALF / 4) / ITH; ++q) {
        int idx = tid + q * ITH;
        int k   = idx & (m - 1);
        int jm  = idx - k;

        float ar = xr[idx],        ai = xi[idx];
        float br = xr[idx + 1024], bi = xi[idx + 1024];
        float cr = xr[idx + 2048], ci = xi[idx + 2048];
        float dr = xr[idx + 3072], di = xi[idx + 3072];

        float t0r = ar + cr, t0i = ai + ci;
        float t1r = ar - cr, t1i = ai - ci;
        float t2r = br + dr, t2i = bi + di;
        float ur  = br - dr, ui  = bi - di;
        float t3r = -ui, t3i = ur;                  // inverse: *(+i)

        float2 w  = g_tw[jm << 1];
        float w1r = w.x, w1i = -w.y;                // conj: inverse
        float w2r = w1r * w1r - w1i * w1i;
        float w2i = 2.0f * w1r * w1i;
        float w3r = w2r * w1r - w2i * w1i;
        float w3i = w2r * w1i + w2i * w1r;

        int o = idx + 3 * jm;
        yr[o]         = t0r + t2r;
        yi[o]         = t0i + t2i;
        float e1r = t1r + t3r, e1i = t1i + t3i;
        yr[o + m]     = e1r * w1r - e1i * w1i;
        yi[o + m]     = e1r * w1i + e1i * w1r;
        float e2r = t0r - t2r, e2i = t0i - t2i;
        yr[o + 2 * m] = e2r * w2r - e2i * w2i;
        yi[o + 2 * m] = e2r * w2i + e2i * w2r;
        float e3r = t1r - t3r, e3i = t1i - t3i;
        yr[o + 3 * m] = e3r * w3r - e3i * w3i;
        yi[o + 3 * m] = e3r * w3i + e3i * w3r;
    }
}

// ---------------------------------------------------------------------------
// Inverse half-spectrum CWT kernel. Two CTAs per (b, s): even / odd samples.
//   G[k] = F[k] * wft[k] / 8192, supported on k=0..4096 only.
//   even CTA: x[2u]   = IDFT4096(G[0..4095])[u]            + G[4096]
//   odd  CTA: x[2u+1] = IDFT4096(G[k]*e^{+i pi k/4096})[u] - G[4096]
// First radix-4 stage fused with load/multiply; last stage fused with
// log|.| + store of only the needed half of the output lines.
// ---------------------------------------------------------------------------
__global__ void __launch_bounds__(ITH, 2)
cwt_ifft_kernel(const float* __restrict__ wft, float* __restrict__ out, int S)
{
    extern __shared__ float sm[];
    float* Ar = sm;
    float* Ai = sm + HALF;
    float* Br = sm + 2 * HALF;
    float* Bi = sm + 3 * HALF;

    const int  tid  = threadIdx.x;
    const int  pair = blockIdx.x >> 1;
    const bool odd  = blockIdx.x & 1;
    const int  s    = pair % S;
    const int  b    = pair / S;

    const float2* F = g_F + b * N_FFT;
    const float*  w = wft + (size_t)s * N_FFT;
    const float inv_n = 1.0f / (float)N_FFT;

    // ---- stage 1 (m=1) fused with global load + spectrum multiply ----
    #pragma unroll
    for (int q = 0; q < 2; ++q) {
        int idx = tid + q * ITH;                 // 0..1023
        float re[4], im[4];
        #pragma unroll
        for (int j = 0; j < 4; ++j) {
            int k = idx + j * 1024;
            float2 f = F[k];
            float  g = w[k] * inv_n;
            float vr = f.x * g, vi = f.y * g;
            if (odd) {                           // * e^{+2 pi i k/8192}
                float2 c = g_tw[k];
                float r2 = vr * c.x + vi * c.y;
                float i2 = vi * c.x - vr * c.y;
                vr = r2; vi = i2;
            }
            re[j] = vr; im[j] = vi;
        }
        float t0r = re[0] + re[2], t0i = im[0] + im[2];
        float t1r = re[0] - re[2], t1i = im[0] - im[2];
        float t2r = re[1] + re[3], t2i = im[1] + im[3];
        float ur  = re[1] - re[3], ui  = im[1] - im[3];
        float t3r = -ui, t3i = ur;

        float2 tw = g_tw[idx << 1];
        float w1r = tw.x, w1i = -tw.y;
        float w2r = w1r * w1r - w1i * w1i;
        float w2i = 2.0f * w1r * w1i;
        float w3r = w2r * w1r - w2i * w1i;
        float w3i = w2r * w1i + w2i * w1r;

        int o = idx << 2;
        Ar[o]     = t0r + t2r;
        Ai[o]     = t0i + t2i;
        float e1r = t1r + t3r, e1i = t1i + t3i;
        Ar[o + 1] = e1r * w1r - e1i * w1i;
        Ai[o + 1] = e1r * w1i + e1i * w1r;
        float e2r = t0r - t2r, e2i = t0i - t2i;
        Ar[o + 2] = e2r * w2r - e2i * w2i;
        Ai[o + 2] = e2r * w2i + e2i * w2r;
        float e3r = t1r - t3r, e3i = t1i - t3i;
        Ar[o + 3] = e3r * w3r - e3i * w3i;
        Ai[o + 3] = e3r * w3i + e3i * w3r;
    }
    __syncthreads();

    r4i_4k(Ar, Ai, Br, Bi, 2, tid); __syncthreads();   // m=4
    r4i_4k(Br, Bi, Ar, Ai, 4, tid); __syncthreads();   // m=16
    r4i_4k(Ar, Ai, Br, Bi, 6, tid); __syncthreads();   // m=64
    r4i_4k(Br, Bi, Ar, Ai, 8, tid); __syncthreads();   // m=256

    // ---- final stage (m=1024, w=1) fused with Nyquist term + log|.| + store
    // Needed outputs: u in [1024,3072) -> output lines j=1 (t1+t3), j=2 (t0-t2).
    float2 fn = F[4096];
    float  gn = w[4096] * inv_n;
    float  nr = fn.x * gn, ni = fn.y * gn;
    if (odd) { nr = -nr; ni = -ni; }

    float* o_ = out + (size_t)pair * T_LEN + (odd ? 1 : 0);
    #pragma unroll
    for (int q = 0; q < 2; ++q) {
        int idx = tid + q * ITH;                 // 0..1023
        float ar = Ar[idx],        ai = Ai[idx];
        float br = Ar[idx + 1024], bi = Ai[idx + 1024];
        float cr = Ar[idx + 2048], ci = Ai[idx + 2048];
        float dr = Ar[idx + 3072], di = Ai[idx + 3072];

        float t0r = ar + cr, t0i = ai + ci;
        float t1r = ar - cr, t1i = ai - ci;
        float t2r = br + dr, t2i = bi + di;
        float ur  = br - dr, ui  = bi - di;
        float t3r = -ui, t3i = ur;

        // u = idx + 1024  ->  t = 2u(+1)  ->  out index 2*idx (+odd offset)
        float x1r = t1r + t3r + nr, x1i = t1i + t3i + ni;
        // u = idx + 2048  ->  out index 2*idx + 2048
        float x2r = t0r - t2r + nr, x2i = t0i - t2i + ni;

        o_[2 * idx]        = 0.5f * logf(x1r * x1r + x1i * x1i);
        o_[2 * idx + 2048] = 0.5f * logf(x2r * x2r + x2i * x2i);
    }
}

// ---------------------------------------------------------------------------
extern "C" void kernel_launch(void* const* d_in, const int* in_sizes, int n_in,
                              void* d_out, int out_size)
{
    const float* in  = (const float*)d_in[0];
    const float* wft = (const float*)d_in[1];
    float* out = (float*)d_out;

    const int B = in_sizes[0] / T_LEN;     // 64
    const int S = in_sizes[1] / N_FFT;     // 75

    const int fwd_smem  = 4 * N_FFT * sizeof(float);   // 128 KB
    const int ifft_smem = 4 * HALF  * sizeof(float);   //  64 KB
    cudaFuncSetAttribute(fwd_fft_kernel,
                         cudaFuncAttributeMaxDynamicSharedMemorySize, fwd_smem);
    cudaFuncSetAttribute(cwt_ifft_kernel,
                         cudaFuncAttributeMaxDynamicSharedMemorySize, ifft_smem);

    twiddle_init_kernel<<<8, 512>>>();
    fwd_fft_kernel<<<B, FTH, fwd_smem>>>(in);
    cwt_ifft_kernel<<<B * S * 2, ITH, ifft_smem>>>(wft, out, S);
}

// round 3
// speedup vs baseline: 2.0940x; 1.2251x over previous
#include <cuda_runtime.h>

#define N_FWD  8192
#define N_INV  4096
#define T_LEN  4096
#define PAD    2048
#define B_MAX  64
#define FROW   4104           // g_F row stride in float2 (4097 rounded up)
#define FTH    1024
#define ITH    512

// Padded smem indexing: conflict-free radix-8 Stockham writes.
#define PHYS(i) ((i) + ((i) >> 3))
#define FWD_PAD 9216          // PHYS(8191)=9214 -> 9216
#define INV_PAD 4608          // PHYS(4095)=4606 -> 4608

__device__ float2 g_tw[4096];             // e^{-2*pi*i*k/8192}, k in [0,4096)
__device__ float2 g_F[B_MAX * FROW];      // half spectra F[k], k in [0,4096]

// ---------------------------------------------------------------------------
__global__ void twiddle_init_kernel() {
    int k = blockIdx.x * blockDim.x + threadIdx.x;
    if (k < 4096) {
        float s, c;
        sincospif((float)k * (1.0f / 4096.0f), &s, &c);
        g_tw[k] = make_float2(c, -s);
    }
}

// ---------------------------------------------------------------------------
// In-register radix-8 butterfly. FWD: X_r = sum_j x_j e^{-2pi i jr/8};
// INV: e^{+...}. Results left in x[0..7] indexed by r.
// ---------------------------------------------------------------------------
template<bool FWD>
__device__ __forceinline__ void bfly8(float* xr, float* xi)
{
    const float C = 0.70710678118654752440f;
    float t0r=xr[0]+xr[4], t0i=xi[0]+xi[4];
    float t4r=xr[0]-xr[4], t4i=xi[0]-xi[4];
    float t1r=xr[1]+xr[5], t1i=xi[1]+xi[5];
    float t5r=xr[1]-xr[5], t5i=xi[1]-xi[5];
    float t2r=xr[2]+xr[6], t2i=xi[2]+xi[6];
    float t6r=xr[2]-xr[6], t6i=xi[2]-xi[6];
    float t3r=xr[3]+xr[7], t3i=xi[3]+xi[7];
    float t7r=xr[3]-xr[7], t7i=xi[3]-xi[7];

    // even half: radix-4 on (t0,t1,t2,t3) -> X0,X2,X4,X6
    float u0r=t0r+t2r, u0i=t0i+t2i;
    float u1r=t0r-t2r, u1i=t0i-t2i;
    float u2r=t1r+t3r, u2i=t1i+t3i;
    float u3r=t1r-t3r, u3i=t1i-t3i;
    xr[0]=u0r+u2r; xi[0]=u0i+u2i;
    xr[4]=u0r-u2r; xi[4]=u0i-u2i;
    if (FWD) { xr[2]=u1r+u3i; xi[2]=u1i-u3r; xr[6]=u1r-u3i; xi[6]=u1i+u3r; }
    else     { xr[2]=u1r-u3i; xi[2]=u1i+u3r; xr[6]=u1r+u3i; xi[6]=u1i-u3r; }

    // odd half: pre-rotate by 8th roots then radix-4 -> X1,X3,X5,X7
    float a5r,a5i,a6r,a6i,a7r,a7i;
    if (FWD) {
        a5r =  C*(t5r+t5i);  a5i =  C*(t5i-t5r);    // e^{-i pi/4}
        a6r =  t6i;          a6i = -t6r;            // -i
        a7r =  C*(t7i-t7r);  a7i = -C*(t7r+t7i);    // e^{-3i pi/4}
    } else {
        a5r =  C*(t5r-t5i);  a5i =  C*(t5r+t5i);    // e^{+i pi/4}
        a6r = -t6i;          a6i =  t6r;            // +i
        a7r = -C*(t7r+t7i);  a7i =  C*(t7r-t7i);    // e^{+3i pi/4}
    }
    float v0r=t4r+a6r, v0i=t4i+a6i;
    float v1r=t4r-a6r, v1i=t4i-a6i;
    float v2r=a5r+a7r, v2i=a5i+a7i;
    float v3r=a5r-a7r, v3i=a5i-a7i;
    xr[1]=v0r+v2r; xi[1]=v0i+v2i;
    xr[5]=v0r-v2r; xi[5]=v0i-v2i;
    if (FWD) { xr[3]=v1r+v3i; xi[3]=v1i-v3r; xr[7]=v1r-v3i; xi[7]=v1i+v3r; }
    else     { xr[3]=v1r-v3i; xi[3]=v1i+v3r; xr[7]=v1r+v3i; xi[7]=v1i-v3r; }
}

// Store 8 butterfly outputs with twiddles w1^r to padded smem.
__device__ __forceinline__ void store8(float* dr, float* di,
                                       const float* xr, const float* xi,
                                       int o, int m, float w1r, float w1i)
{
    float cr = 1.0f, ci = 0.0f;
    #pragma unroll
    for (int r = 0; r < 8; ++r) {
        int p = PHYS(o + r * m);
        dr[p] = xr[r] * cr - xi[r] * ci;
        di[p] = xr[r] * ci + xi[r] * cr;
        float nr = cr * w1r - ci * w1i;
        ci = cr * w1i + ci * w1r;
        cr = nr;
    }
}

// ---------------------------------------------------------------------------
// Forward 8192-pt FFT (radix-8 x4 + radix-2), one CTA per batch row.
// Stores only F[0..4096] (half spectrum; wft kills negative freqs).
// ---------------------------------------------------------------------------
__device__ __forceinline__ void fwd_stage(const float* sr, const float* si,
                                          float* dr, float* di, int m, int tid)
{
    float xr[8], xi[8];
    #pragma unroll
    for (int q = 0; q < 8; ++q) {
        int p = PHYS(tid + q * 1024);
        xr[q] = sr[p]; xi[q] = si[p];
    }
    bfly8<true>(xr, xi);
    int k = tid & (m - 1), jm = tid - k;
    float2 t = g_tw[jm];
    store8(dr, di, xr, xi, 8 * jm + k, m, t.x, t.y);
}

extern __shared__ float sm_[];

__global__ void __launch_bounds__(FTH, 1)
fwd_fft_kernel(const float* __restrict__ in)
{
    float* Ar = sm_;
    float* Ai = sm_ + FWD_PAD;
    float* Br = sm_ + 2 * FWD_PAD;
    float* Bi = sm_ + 3 * FWD_PAD;

    const int b = blockIdx.x, tid = threadIdx.x;
    const float* x = in + b * T_LEN;

    // stage m=1 fused with reflect-pad load
    {
        float xr[8], xi[8];
        #pragma unroll
        for (int q = 0; q < 8; ++q) {
            int i = tid + q * 1024;
            int src;
            if (i < PAD)              src = PAD - 1 - i;
            else if (i < PAD + T_LEN) src = i - PAD;
            else                      src = (2 * T_LEN + PAD - 1) - i;
            xr[q] = x[src]; xi[q] = 0.0f;
        }
        bfly8<true>(xr, xi);
        float2 t = g_tw[tid];
        store8(Ar, Ai, xr, xi, 8 * tid, 1, t.x, t.y);
    }
    __syncthreads();
    fwd_stage(Ar, Ai, Br, Bi,   8, tid); __syncthreads();
    fwd_stage(Br, Bi, Ar, Ai,  64, tid); __syncthreads();
    fwd_stage(Ar, Ai, Br, Bi, 512, tid); __syncthreads();

    // final radix-2 (m=4096, w=1): keep only k in [0,4096]
    float2* Fo = g_F + b * FROW;
    #pragma unroll
    for (int q = 0; q < 4; ++q) {
        int k = tid + q * 1024;
        float ur = Br[PHYS(k)],        ui = Bi[PHYS(k)];
        float vr = Br[PHYS(k + 4096)], vi = Bi[PHYS(k + 4096)];
        Fo[k] = make_float2(ur + vr, ui + vi);
        if (k == 0) Fo[4096] = make_float2(ur - vr, ui - vi);
    }
}

// ---------------------------------------------------------------------------
// CWT inverse kernel: one CTA per (b,s). Two sequential 4096-pt inverse
// radix-8 Stockham FFTs (even / odd output samples of the 8192 IFFT, using
// the half-spectrum support of G = F*wft/8192). Even pass stashes its log
// magnitudes in smem; odd pass emits coalesced float2 stores.
// ---------------------------------------------------------------------------
__device__ __forceinline__ void inv_stage(const float* sr, const float* si,
                                          float* dr, float* di, int m, int tid)
{
    float xr[8], xi[8];
    #pragma unroll
    for (int q = 0; q < 8; ++q) {
        int p = PHYS(tid + q * 512);
        xr[q] = sr[p]; xi[q] = si[p];
    }
    bfly8<false>(xr, xi);
    int k = tid & (m - 1), jm = tid - k;
    float2 t = g_tw[jm << 1];             // e^{-2pi i jm/4096}; conj below
    store8(dr, di, xr, xi, 8 * jm + k, m, t.x, -t.y);
}

__global__ void __launch_bounds__(ITH, 2)
cwt_kernel(const float* __restrict__ wft, float* __restrict__ out, int S)
{
    float* Ar    = sm_;
    float* Ai    = sm_ + INV_PAD;
    float* Br    = sm_ + 2 * INV_PAD;
    float* Bi    = sm_ + 3 * INV_PAD;
    float* stash = sm_ + 4 * INV_PAD;     // 2048 floats

    const int tid = threadIdx.x;
    const int s = blockIdx.x % S, b = blockIdx.x / S;
    const float2* __restrict__ F = g_F + b * FROW;
    const float*  __restrict__ w = wft + (size_t)s * N_FWD;
    const float inv_n = 1.0f / 8192.0f;

    float2 fn = F[4096];
    float  gn = w[4096] * inv_n;
    float  nyr = fn.x * gn, nyi = fn.y * gn;

    #pragma unroll
    for (int pass = 0; pass < 2; ++pass) {
        float xr[8], xi[8];

        // stage m=1 fused with global load + spectrum multiply (+odd rotation)
        #pragma unroll
        for (int q = 0; q < 8; ++q) {
            int k = tid + q * 512;
            float2 f = F[k];
            float  g = w[k] * inv_n;
            float vr = f.x * g, vi = f.y * g;
            if (pass) {                        // * e^{+2 pi i k/8192}
                float2 c = g_tw[k];
                float r2 = vr * c.x + vi * c.y;
                float i2 = vi * c.x - vr * c.y;
                vr = r2; vi = i2;
            }
            xr[q] = vr; xi[q] = vi;
        }
        bfly8<false>(xr, xi);
        {
            float2 t = g_tw[tid << 1];
            store8(Ar, Ai, xr, xi, 8 * tid, 1, t.x, -t.y);
        }
        __syncthreads();
        inv_stage(Ar, Ai, Br, Bi,  8, tid); __syncthreads();
        inv_stage(Br, Bi, Ar, Ai, 64, tid); __syncthreads();

        // final stage m=512 (jm=0, w=1) fused with Nyquist + log|.| + store.
        // Thread tid produces u = tid + 512 r; needed u in [1024,3072) -> r=2..5.
        #pragma unroll
        for (int q = 0; q < 8; ++q) {
            int p = PHYS(tid + q * 512);
            xr[q] = Ar[p]; xi[q] = Ai[p];
        }
        bfly8<false>(xr, xi);

        float nr = pass ? -nyr : nyr;
        float ni = pass ? -nyi : nyi;
        if (pass == 0) {
            #pragma unroll
            for (int r = 2; r <= 5; ++r) {
                float a = xr[r] + nr, bb = xi[r] + ni;
                stash[tid + 512 * (r - 2)] = 0.5f * logf(a * a + bb * bb);
            }
        } else {
            float2* o2 = (float2*)(out + (size_t)blockIdx.x * T_LEN);
            #pragma unroll
            for (int r = 2; r <= 5; ++r) {
                float a = xr[r] + nr, bb = xi[r] + ni;
                float lg = 0.5f * logf(a * a + bb * bb);
                int c = tid + 512 * (r - 2);
                o2[c] = make_float2(stash[c], lg);
            }
        }
        __syncthreads();
    }
}

// ---------------------------------------------------------------------------
extern "C" void kernel_launch(void* const* d_in, const int* in_sizes, int n_in,
                              void* d_out, int out_size)
{
    const float* in  = (const float*)d_in[0];
    const float* wft = (const float*)d_in[1];
    float* out = (float*)d_out;

    const int B = in_sizes[0] / T_LEN;     // 64
    const int S = in_sizes[1] / N_FWD;     // 75

    const int fwd_smem = 4 * FWD_PAD * sizeof(float);              // 147456 B
    const int cwt_smem = (4 * INV_PAD + 2048) * sizeof(float);     //  81920 B
    cudaFuncSetAttribute(fwd_fft_kernel,
                         cudaFuncAttributeMaxDynamicSharedMemorySize, fwd_smem);
    cudaFuncSetAttribute(cwt_kernel,
                         cudaFuncAttributeMaxDynamicSharedMemorySize, cwt_smem);

    twiddle_init_kernel<<<16, 256>>>();
    fwd_fft_kernel<<<B, FTH, fwd_smem>>>(in);
    cwt_kernel<<<B * S, ITH, cwt_smem>>>(wft, out, S);
}